// round 2
// baseline (speedup 1.0000x reference)
#include <cuda_runtime.h>

#define NG 128
#define FEAT 16
#define WIDTH 64
#define NUM_POS 3
#define IN_MLP 25          // FEAT + NUM_POS*3
#define MAX_PTS 262144
#define NB 32768           // 32x32x32 spatial buckets (4^3 grid cells each)

// ---- scratch (device globals per harness rules) ----
__device__ float  g_feat[MAX_PTS * FEAT];   // interpolated features, sorted order
__device__ float4 g_tpos[MAX_PTS];          // (tx,ty,tz, orig-index-as-bits), sorted order
__device__ int    g_hist[NB];
__device__ int    g_base[NB];
__device__ int    g_key [MAX_PTS];
__device__ int    g_rank[MAX_PTS];
__device__ int    g_order[MAX_PTS];

// ---- packed f32x2 helpers (sm_10x) ----
__device__ __forceinline__ unsigned long long pack2(float a, float b) {
    unsigned long long r;
    asm("mov.b64 %0, {%1, %2};" : "=l"(r) : "f"(a), "f"(b));
    return r;
}
__device__ __forceinline__ void unpack2(unsigned long long v, float& a, float& b) {
    asm("mov.b64 {%0, %1}, %2;" : "=f"(a), "=f"(b) : "l"(v));
}
__device__ __forceinline__ unsigned long long fma2(unsigned long long a,
                                                   unsigned long long b,
                                                   unsigned long long c) {
    unsigned long long d;
    asm("fma.rn.f32x2 %0, %1, %2, %3;" : "=l"(d) : "l"(a), "l"(b), "l"(c));
    return d;
}

__device__ __forceinline__ void cubic_w(float t, float w[4]) {
    float t2 = t * t, t3 = t2 * t;
    w[0] = 0.5f * (-t3 + 2.0f * t2 - t);
    w[1] = 0.5f * (3.0f * t3 - 5.0f * t2 + 2.0f);
    w[2] = 0.5f * (-3.0f * t3 + 4.0f * t2 + t);
    w[3] = 0.5f * (t3 - t2);
}

// ================= sorting passes =================

__global__ __launch_bounds__(256) void zero_hist_kernel() {
    int i = blockIdx.x * 256 + threadIdx.x;
    if (i < NB) g_hist[i] = 0;
}

__global__ __launch_bounds__(256) void hist_kernel(const float* __restrict__ x, int npts) {
    int pt = blockIdx.x * 256 + threadIdx.x;
    if (pt >= npts) return;
    int ix = (int)floorf(x[3 * pt + 0] * 127.0f);
    int iy = (int)floorf(x[3 * pt + 1] * 127.0f);
    int iz = (int)floorf(x[3 * pt + 2] * 127.0f);
    ix = min(max(ix, 0), 126); iy = min(max(iy, 0), 126); iz = min(max(iz, 0), 126);
    int key = ((ix >> 2) << 10) | ((iy >> 2) << 5) | (iz >> 2);
    int rank = atomicAdd(&g_hist[key], 1);
    g_key[pt] = key;
    g_rank[pt] = rank;
}

__global__ __launch_bounds__(1024) void scan_kernel() {
    __shared__ int s[1024];
    int tid = threadIdx.x;
    int base = tid * 32;
    int local[32];
    int sum = 0;
    #pragma unroll
    for (int i = 0; i < 32; i++) { local[i] = sum; sum += g_hist[base + i]; }
    s[tid] = sum;
    __syncthreads();
    for (int off = 1; off < 1024; off <<= 1) {
        int v = (tid >= off) ? s[tid - off] : 0;
        __syncthreads();
        s[tid] += v;
        __syncthreads();
    }
    int chunk = (tid > 0) ? s[tid - 1] : 0;
    #pragma unroll
    for (int i = 0; i < 32; i++) g_base[base + i] = chunk + local[i];
}

__global__ __launch_bounds__(256) void scatter_kernel(int npts) {
    int pt = blockIdx.x * 256 + threadIdx.x;
    if (pt >= npts) return;
    int pos = g_base[g_key[pt]] + g_rank[pt];
    g_order[pos] = pt;
}

// ================= tricubic gather (sorted order) =================
// 16 lanes per point: lane = (c, fg), c = z-tap (0..3), fg = feature float4 (0..3).
__global__ __launch_bounds__(256) void gather_kernel(
    const float* __restrict__ x,
    const float* __restrict__ grid,
    int npts)
{
    int gtid = blockIdx.x * 256 + threadIdx.x;
    int spt = gtid >> 4;
    if (spt >= npts) return;
    int sub = gtid & 15;
    int c  = sub >> 2;
    int fg = sub & 3;

    int pt = g_order[spt];
    float ux = x[3 * pt + 0] * 127.0f;
    float uy = x[3 * pt + 1] * 127.0f;
    float uz = x[3 * pt + 2] * 127.0f;
    float fx = floorf(ux), fy = floorf(uy), fz = floorf(uz);
    float tx = ux - fx, ty = uy - fy, tz = uz - fz;
    int ix0 = (int)fx, iy0 = (int)fy, iz0 = (int)fz;

    float wx[4], wy[4], wz[4];
    cubic_w(tx, wx);
    cubic_w(ty, wy);
    cubic_w(tz, wz);
    float wzc = wz[c];
    int zi = min(max(iz0 + c - 1, 0), NG - 1);

    float4 acc = make_float4(0.f, 0.f, 0.f, 0.f);
    #pragma unroll
    for (int a = 0; a < 4; a++) {
        int xi = min(max(ix0 + a - 1, 0), NG - 1);
        const float* gx = grid + (size_t)xi * (NG * NG * FEAT);
        float wxa = wx[a];
        #pragma unroll
        for (int b = 0; b < 4; b++) {
            int yi = min(max(iy0 + b - 1, 0), NG - 1);
            float w = wxa * wy[b] * wzc;
            const float4* gp =
                reinterpret_cast<const float4*>(gx + (yi * NG + zi) * FEAT) + fg;
            float4 v = __ldg(gp);
            acc.x += w * v.x;
            acc.y += w * v.y;
            acc.z += w * v.z;
            acc.w += w * v.w;
        }
    }

    const unsigned m = 0xFFFFFFFFu;
    acc.x += __shfl_xor_sync(m, acc.x, 4);
    acc.y += __shfl_xor_sync(m, acc.y, 4);
    acc.z += __shfl_xor_sync(m, acc.z, 4);
    acc.w += __shfl_xor_sync(m, acc.w, 4);
    acc.x += __shfl_xor_sync(m, acc.x, 8);
    acc.y += __shfl_xor_sync(m, acc.y, 8);
    acc.z += __shfl_xor_sync(m, acc.z, 8);
    acc.w += __shfl_xor_sync(m, acc.w, 8);

    if (sub == 0) g_tpos[spt] = make_float4(tx, ty, tz, __int_as_float(pt));
    if (c == 0)
        reinterpret_cast<float4*>(g_feat)[spt * 4 + fg] = acc;
}

// ================= MLP: 2 points per thread, packed f32x2 =================
__global__ __launch_bounds__(256) void mlp_kernel(
    const float* __restrict__ w1,
    const float* __restrict__ b1,
    const float* __restrict__ w2,
    const float* __restrict__ b2,
    float* __restrict__ out,
    int npts)
{
    __shared__ float2 s_w1d[WIDTH][IN_MLP];  // duplicated (w,w) pairs: 12.8 KB
    __shared__ float2 s_b1d[WIDTH];
    __shared__ float  s_w2[WIDTH];
    __shared__ float  s_b2;

    for (int i = threadIdx.x; i < WIDTH * IN_MLP; i += 256) {
        float v = w1[i];
        s_w1d[i / IN_MLP][i % IN_MLP] = make_float2(v, v);
    }
    if (threadIdx.x < WIDTH) {
        float bv = b1[threadIdx.x];
        s_b1d[threadIdx.x] = make_float2(bv, bv);
        s_w2[threadIdx.x]  = w2[threadIdx.x];
    }
    if (threadIdx.x == 0) s_b2 = b2[0];
    __syncthreads();

    int warp = (blockIdx.x * 256 + threadIdx.x) >> 5;
    int lane = threadIdx.x & 31;
    int base = warp * 64;
    int sA = base + lane;
    int sB = base + lane + 32;
    if (sA >= npts) return;
    bool hasB = (sB < npts);
    int sBr = hasB ? sB : sA;

    unsigned long long h2[IN_MLP];
    {
        const float4* fa = reinterpret_cast<const float4*>(g_feat) + sA * 4;
        const float4* fb = reinterpret_cast<const float4*>(g_feat) + sBr * 4;
        #pragma unroll
        for (int g = 0; g < 4; g++) {
            float4 va = fa[g], vb = fb[g];
            h2[g * 4 + 0] = pack2(va.x, vb.x);
            h2[g * 4 + 1] = pack2(va.y, vb.y);
            h2[g * 4 + 2] = pack2(va.z, vb.z);
            h2[g * 4 + 3] = pack2(va.w, vb.w);
        }
    }
    float4 tpA = g_tpos[sA];
    float4 tpB = g_tpos[sBr];
    {
        const float TWO_PI = 6.283185307179586f;
        float ta[3] = {tpA.x, tpA.y, tpA.z};
        float tb[3] = {tpB.x, tpB.y, tpB.z};
        #pragma unroll
        for (int k = 0; k < NUM_POS; k++) {
            #pragma unroll
            for (int d = 0; d < 3; d++) {
                float va = __sinf(TWO_PI * (float)(k + 1) * ta[d]);
                float vb = __sinf(TWO_PI * (float)(k + 1) * tb[d]);
                h2[FEAT + 3 * k + d] = pack2(va, vb);
            }
        }
    }

    float accA = s_b2, accB = s_b2;
    #pragma unroll 4
    for (int j = 0; j < WIDTH; j++) {
        const unsigned long long* wrow =
            reinterpret_cast<const unsigned long long*>(s_w1d[j]);
        unsigned long long s2 =
            *reinterpret_cast<const unsigned long long*>(&s_b1d[j]);
        #pragma unroll
        for (int i = 0; i < IN_MLP; i++)
            s2 = fma2(wrow[i], h2[i], s2);
        float sa, sb;
        unpack2(s2, sa, sb);
        float siga = __fdividef(1.0f, 1.0f + __expf(-sa));
        float sigb = __fdividef(1.0f, 1.0f + __expf(-sb));
        float w2j = s_w2[j];
        accA += w2j * (sa * siga);
        accB += w2j * (sb * sigb);
    }

    out[__float_as_int(tpA.w)] = accA;
    if (hasB) out[__float_as_int(tpB.w)] = accB;
}

extern "C" void kernel_launch(void* const* d_in, const int* in_sizes, int n_in,
                              void* d_out, int out_size) {
    const float* x    = (const float*)d_in[0];
    const float* grid = (const float*)d_in[1];
    const float* w1   = (const float*)d_in[2];
    const float* b1   = (const float*)d_in[3];
    const float* w2   = (const float*)d_in[4];
    const float* b2   = (const float*)d_in[5];
    float* out = (float*)d_out;

    int npts = in_sizes[0] / 3;
    if (npts > MAX_PTS) npts = MAX_PTS;

    zero_hist_kernel<<<NB / 256, 256>>>();
    int pblocks = (npts + 255) / 256;
    hist_kernel<<<pblocks, 256>>>(x, npts);
    scan_kernel<<<1, 1024>>>();
    scatter_kernel<<<pblocks, 256>>>(npts);

    int gblocks = (npts * 16 + 255) / 256;
    gather_kernel<<<gblocks, 256>>>(x, grid, npts);

    int mblocks = (npts + 511) / 512;  // 2 points/thread
    mlp_kernel<<<mblocks, 256>>>(w1, b1, w2, b2, out, npts);
}

// round 3
// speedup vs baseline: 1.0463x; 1.0463x over previous
#include <cuda_runtime.h>

#define NG 128
#define FEAT 16
#define WIDTH 64
#define NUM_POS 3
#define IN_MLP 25          // FEAT + NUM_POS*3
#define MAX_PTS 262144
#define NB 32768           // 32x32x32 spatial buckets (4^3 grid cells each)

// ---- scratch (device globals per harness rules) ----
__device__ float  g_feat[MAX_PTS * FEAT];   // interpolated features, sorted order
__device__ float4 g_tpos[MAX_PTS];          // (tx,ty,tz, orig-index-as-bits), sorted order
__device__ int    g_hist[NB];
__device__ int    g_base[NB];
__device__ int    g_key [MAX_PTS];
__device__ int    g_rank[MAX_PTS];
__device__ int    g_order[MAX_PTS];

// ---- packed f32x2 helpers (sm_10x) ----
__device__ __forceinline__ unsigned long long pack2(float a, float b) {
    unsigned long long r;
    asm("mov.b64 %0, {%1, %2};" : "=l"(r) : "f"(a), "f"(b));
    return r;
}
__device__ __forceinline__ void unpack2(unsigned long long v, float& a, float& b) {
    asm("mov.b64 {%0, %1}, %2;" : "=f"(a), "=f"(b) : "l"(v));
}
__device__ __forceinline__ unsigned long long fma2(unsigned long long a,
                                                   unsigned long long b,
                                                   unsigned long long c) {
    unsigned long long d;
    asm("fma.rn.f32x2 %0, %1, %2, %3;" : "=l"(d) : "l"(a), "l"(b), "l"(c));
    return d;
}

__device__ __forceinline__ void cubic_w(float t, float w[4]) {
    float t2 = t * t, t3 = t2 * t;
    w[0] = 0.5f * (-t3 + 2.0f * t2 - t);
    w[1] = 0.5f * (3.0f * t3 - 5.0f * t2 + 2.0f);
    w[2] = 0.5f * (-3.0f * t3 + 4.0f * t2 + t);
    w[3] = 0.5f * (t3 - t2);
}

// ================= sorting passes =================

__global__ __launch_bounds__(256) void zero_hist_kernel() {
    int i = blockIdx.x * 256 + threadIdx.x;
    if (i < NB) g_hist[i] = 0;
}

__global__ __launch_bounds__(256) void hist_kernel(const float* __restrict__ x, int npts) {
    int pt = blockIdx.x * 256 + threadIdx.x;
    if (pt >= npts) return;
    int ix = (int)floorf(x[3 * pt + 0] * 127.0f);
    int iy = (int)floorf(x[3 * pt + 1] * 127.0f);
    int iz = (int)floorf(x[3 * pt + 2] * 127.0f);
    ix = min(max(ix, 0), 126); iy = min(max(iy, 0), 126); iz = min(max(iz, 0), 126);
    int key = ((ix >> 2) << 10) | ((iy >> 2) << 5) | (iz >> 2);
    int rank = atomicAdd(&g_hist[key], 1);
    g_key[pt] = key;
    g_rank[pt] = rank;
}

__global__ __launch_bounds__(1024) void scan_kernel() {
    __shared__ int s[1024];
    int tid = threadIdx.x;
    int base = tid * 32;
    int local[32];
    int sum = 0;
    #pragma unroll
    for (int i = 0; i < 32; i++) { local[i] = sum; sum += g_hist[base + i]; }
    s[tid] = sum;
    __syncthreads();
    for (int off = 1; off < 1024; off <<= 1) {
        int v = (tid >= off) ? s[tid - off] : 0;
        __syncthreads();
        s[tid] += v;
        __syncthreads();
    }
    int chunk = (tid > 0) ? s[tid - 1] : 0;
    #pragma unroll
    for (int i = 0; i < 32; i++) g_base[base + i] = chunk + local[i];
}

__global__ __launch_bounds__(256) void scatter_kernel(int npts) {
    int pt = blockIdx.x * 256 + threadIdx.x;
    if (pt >= npts) return;
    int pos = g_base[g_key[pt]] + g_rank[pt];
    g_order[pos] = pt;
}

// ================= tricubic gather (sorted order) =================
// 16 lanes per point: lane = (c, fg), c = z-tap (0..3), fg = feature float4 (0..3).
__global__ __launch_bounds__(256) void gather_kernel(
    const float* __restrict__ x,
    const float* __restrict__ grid,
    int npts)
{
    int gtid = blockIdx.x * 256 + threadIdx.x;
    int spt = gtid >> 4;
    if (spt >= npts) return;
    int sub = gtid & 15;
    int c  = sub >> 2;
    int fg = sub & 3;

    int pt = g_order[spt];
    float ux = x[3 * pt + 0] * 127.0f;
    float uy = x[3 * pt + 1] * 127.0f;
    float uz = x[3 * pt + 2] * 127.0f;
    float fx = floorf(ux), fy = floorf(uy), fz = floorf(uz);
    float tx = ux - fx, ty = uy - fy, tz = uz - fz;
    int ix0 = (int)fx, iy0 = (int)fy, iz0 = (int)fz;

    float wx[4], wy[4], wz[4];
    cubic_w(tx, wx);
    cubic_w(ty, wy);
    cubic_w(tz, wz);
    float wzc = wz[c];
    int zi = min(max(iz0 + c - 1, 0), NG - 1);

    float4 acc = make_float4(0.f, 0.f, 0.f, 0.f);
    #pragma unroll
    for (int a = 0; a < 4; a++) {
        int xi = min(max(ix0 + a - 1, 0), NG - 1);
        const float* gx = grid + (size_t)xi * (NG * NG * FEAT);
        float wxa = wx[a];
        #pragma unroll
        for (int b = 0; b < 4; b++) {
            int yi = min(max(iy0 + b - 1, 0), NG - 1);
            float w = wxa * wy[b] * wzc;
            const float4* gp =
                reinterpret_cast<const float4*>(gx + (yi * NG + zi) * FEAT) + fg;
            float4 v = __ldg(gp);
            acc.x += w * v.x;
            acc.y += w * v.y;
            acc.z += w * v.z;
            acc.w += w * v.w;
        }
    }

    const unsigned m = 0xFFFFFFFFu;
    acc.x += __shfl_xor_sync(m, acc.x, 4);
    acc.y += __shfl_xor_sync(m, acc.y, 4);
    acc.z += __shfl_xor_sync(m, acc.z, 4);
    acc.w += __shfl_xor_sync(m, acc.w, 4);
    acc.x += __shfl_xor_sync(m, acc.x, 8);
    acc.y += __shfl_xor_sync(m, acc.y, 8);
    acc.z += __shfl_xor_sync(m, acc.z, 8);
    acc.w += __shfl_xor_sync(m, acc.w, 8);

    if (sub == 0) g_tpos[spt] = make_float4(tx, ty, tz, __int_as_float(pt));
    if (c == 0)
        reinterpret_cast<float4*>(g_feat)[spt * 4 + fg] = acc;
}

// ================= MLP: 1 point/thread, hidden-unit PAIRS via f32x2 =========
// s_wp[j2][i] = (w1[2*j2][i], w1[2*j2+1][i]) packed 64-bit.
// h duplicated once into 25 packed regs; 25 FMA2 per hidden pair.
__global__ __launch_bounds__(256) void mlp_kernel(
    const float* __restrict__ w1,
    const float* __restrict__ b1,
    const float* __restrict__ w2,
    const float* __restrict__ b2,
    float* __restrict__ out,
    int npts)
{
    __shared__ unsigned long long s_wp[WIDTH / 2][IN_MLP + 1]; // +1 pad, 16B align rows
    __shared__ unsigned long long s_bp[WIDTH / 2];
    __shared__ unsigned long long s_w2p[WIDTH / 2];
    __shared__ float s_b2;

    for (int i = threadIdx.x; i < (WIDTH / 2) * IN_MLP; i += 256) {
        int j2 = i / IN_MLP, ii = i % IN_MLP;
        s_wp[j2][ii] = pack2(w1[(2 * j2) * IN_MLP + ii], w1[(2 * j2 + 1) * IN_MLP + ii]);
    }
    if (threadIdx.x < WIDTH / 2) {
        s_bp[threadIdx.x]  = pack2(b1[2 * threadIdx.x], b1[2 * threadIdx.x + 1]);
        s_w2p[threadIdx.x] = pack2(w2[2 * threadIdx.x], w2[2 * threadIdx.x + 1]);
    }
    if (threadIdx.x == 0) s_b2 = b2[0];
    __syncthreads();

    int n = blockIdx.x * 256 + threadIdx.x;
    if (n >= npts) return;

    // Load features (sorted order) and duplicate into packed regs.
    unsigned long long h2[IN_MLP];
    {
        const float4* fb = reinterpret_cast<const float4*>(g_feat) + n * 4;
        #pragma unroll
        for (int g = 0; g < 4; g++) {
            float4 v = fb[g];
            h2[g * 4 + 0] = pack2(v.x, v.x);
            h2[g * 4 + 1] = pack2(v.y, v.y);
            h2[g * 4 + 2] = pack2(v.z, v.z);
            h2[g * 4 + 3] = pack2(v.w, v.w);
        }
    }
    float4 tp = g_tpos[n];
    {
        const float TWO_PI = 6.283185307179586f;
        float t[3] = {tp.x, tp.y, tp.z};
        #pragma unroll
        for (int k = 0; k < NUM_POS; k++) {
            #pragma unroll
            for (int d = 0; d < 3; d++) {
                float v = __sinf(TWO_PI * (float)(k + 1) * t[d]);
                h2[FEAT + 3 * k + d] = pack2(v, v);
            }
        }
    }

    unsigned long long acc2 = pack2(s_b2, 0.0f);
    #pragma unroll 4
    for (int j2 = 0; j2 < WIDTH / 2; j2++) {
        unsigned long long s2 = s_bp[j2];
        const unsigned long long* wrow = s_wp[j2];
        #pragma unroll
        for (int i = 0; i < IN_MLP; i++)
            s2 = fma2(wrow[i], h2[i], s2);
        float sa, sb;
        unpack2(s2, sa, sb);
        float ga = sa * __fdividef(1.0f, 1.0f + __expf(-sa));
        float gb = sb * __fdividef(1.0f, 1.0f + __expf(-sb));
        acc2 = fma2(s_w2p[j2], pack2(ga, gb), acc2);
    }
    float ra, rb;
    unpack2(acc2, ra, rb);
    out[__float_as_int(tp.w)] = ra + rb;
}

extern "C" void kernel_launch(void* const* d_in, const int* in_sizes, int n_in,
                              void* d_out, int out_size) {
    const float* x    = (const float*)d_in[0];
    const float* grid = (const float*)d_in[1];
    const float* w1   = (const float*)d_in[2];
    const float* b1   = (const float*)d_in[3];
    const float* w2   = (const float*)d_in[4];
    const float* b2   = (const float*)d_in[5];
    float* out = (float*)d_out;

    int npts = in_sizes[0] / 3;
    if (npts > MAX_PTS) npts = MAX_PTS;

    zero_hist_kernel<<<NB / 256, 256>>>();
    int pblocks = (npts + 255) / 256;
    hist_kernel<<<pblocks, 256>>>(x, npts);
    scan_kernel<<<1, 1024>>>();
    scatter_kernel<<<pblocks, 256>>>(npts);

    int gblocks = (npts * 16 + 255) / 256;
    gather_kernel<<<gblocks, 256>>>(x, grid, npts);

    int mblocks = (npts + 255) / 256;
    mlp_kernel<<<mblocks, 256>>>(w1, b1, w2, b2, out, npts);
}